// round 15
// baseline (speedup 1.0000x reference)
#include <cuda_runtime.h>
#include <math.h>

#define NV 778
#define VP 784            // 8*98 verts, 392 pairs
#define NP 392            // vertex pairs
#define NJ 16
#define NCOMP 24
#define NBETA 10
#define FC 1554
#define NA 32
#define NB 8
#define NOBJ 16384

#define NCH 8
#define CPL 49            // pairs per chunk (8*49 = 392)

#define OFF_CMAP 0
#define OFF_PEN  (NB*NOBJ)
#define OFF_VERTS (OFF_PEN + 1)
#define OFF_CC   (OFF_VERTS + NB*NV*3)

// pair-interleaved vertex data:
//  g_vpA[p] = { X=(x0,x1), Y=(y0,y1) }   g_vpB[p] = { Z=(z0,z1), Wn=(wn0,wn1) }
//  wn = -0.5*|v|^2  (sentinel: x=y=z=0, wn=-1e30)
__device__ ulonglong2 g_vpA[NB * NP];
__device__ ulonglong2 g_vpB[NB * NP];
__device__ float  g_normals[NB * NV * 3];  // UNNORMALIZED (sign-only use)

__constant__ int c_parents[NJ] = {-1,0,1,2,0,4,5,0,7,8,0,10,11,0,13,14};

__device__ __forceinline__ unsigned long long pack2(float v) {
    unsigned long long r; unsigned u = __float_as_uint(v);
    asm("mov.b64 %0, {%1, %1};" : "=l"(r) : "r"(u));
    return r;
}
__device__ __forceinline__ void unpack2(unsigned long long v, float& lo, float& hi) {
    unsigned a, b;
    asm("mov.b64 {%0, %1}, %2;" : "=r"(a), "=r"(b) : "l"(v));
    lo = __uint_as_float(a); hi = __uint_as_float(b);
}
#define FMA2(d,a,b,c) asm("fma.rn.f32x2 %0, %1, %2, %3;" : "=l"(d) : "l"(a), "l"(b), "l"(c))

// ---------------------------------------------------------------------------
// vert: FULL pipeline per block (v_shaped + J + pose + chain) + posedirs + LBS
// grid NB*16 (49 verts/block), 256 thr. Also zeroes normals + pen slot.
// ---------------------------------------------------------------------------
__global__ void __launch_bounds__(256) vert_kernel(
    const float* __restrict__ v_template, const float* __restrict__ shapedirs,
    const float* __restrict__ posedirs, const float* __restrict__ lbs_w,
    const float* __restrict__ hand_pose, const float* __restrict__ hand_beta,
    const float* __restrict__ pca, const float* __restrict__ J_reg,
    float* __restrict__ out)
{
    __shared__ float s_pose[32];
    __shared__ float s_beta[NBETA];
    __shared__ float s_full[48];
    __shared__ float s_R[NJ * 9];
    __shared__ float s_J[48];
    __shared__ float s_T[NJ * 12];
    __shared__ float s_A[NJ * 12];
    __shared__ float s_pf[136];
    __shared__ float s_vsh[NV * 3];
    __shared__ float s_vp[49 * 3];

    const int b = blockIdx.x >> 4;
    const int chunk = blockIdx.x & 15;
    const int vbase = chunk * 49;
    const int tid = threadIdx.x;
    const int wid = tid >> 5, lane = tid & 31;

    // phase 0: stage tiny inputs, zero accumulator slices
    if (tid < 30) s_pose[tid] = hand_pose[b * 30 + tid];
    if (tid >= 32 && tid < 32 + NBETA) s_beta[tid - 32] = hand_beta[b * NBETA + (tid - 32)];
    {
        int base = blockIdx.x * 146;
        int end = base + 146; if (end > NB * NV * 3) end = NB * NV * 3;
        for (int i = base + tid; i < end; i += 256) g_normals[i] = 0.f;
    }
    if (blockIdx.x == 0 && tid == 0) out[OFF_PEN] = 0.f;
    __syncthreads();

    // phase 1: pca expansion + full v_shaped
    if (tid < 3) s_full[tid] = s_pose[3 + tid];
    if (tid >= 64 && tid < 64 + 45) {
        int p = tid - 64;
        float acc = 0.f;
        #pragma unroll
        for (int k = 0; k < NCOMP; k++) acc = fmaf(s_pose[6 + k], pca[k * 45 + p], acc);
        s_full[3 + p] = acc;
    }
    for (int i = tid; i < NV * 3; i += 256) {
        const float2* sd = (const float2*)shapedirs + i * 5;
        float2 d0 = sd[0], d1 = sd[1], d2 = sd[2], d3 = sd[3], d4 = sd[4];
        float acc = v_template[i];
        acc = fmaf(d0.x, s_beta[0], acc); acc = fmaf(d0.y, s_beta[1], acc);
        acc = fmaf(d1.x, s_beta[2], acc); acc = fmaf(d1.y, s_beta[3], acc);
        acc = fmaf(d2.x, s_beta[4], acc); acc = fmaf(d2.y, s_beta[5], acc);
        acc = fmaf(d3.x, s_beta[6], acc); acc = fmaf(d3.y, s_beta[7], acc);
        acc = fmaf(d4.x, s_beta[8], acc); acc = fmaf(d4.y, s_beta[9], acc);
        s_vsh[i] = acc;
    }
    __syncthreads();

    // phase 2: rodrigues (tid<16) + J = J_reg @ v_shaped (warp-coop)
    if (tid < NJ) {
        float rx = s_full[tid * 3 + 0], ry = s_full[tid * 3 + 1], rz = s_full[tid * 3 + 2];
        float th = sqrtf(rx * rx + ry * ry + rz * rz + 1e-16f);
        float inv = 1.f / th;
        float kx = rx * inv, ky = ry * inv, kz = rz * inv;
        float c, s;
        sincosf(th, &s, &c);
        float ic = 1.f - c;
        float* R = &s_R[tid * 9];
        R[0] = c + ic * kx * kx;       R[1] = -s * kz + ic * kx * ky; R[2] =  s * ky + ic * kx * kz;
        R[3] =  s * kz + ic * ky * kx; R[4] = c + ic * ky * ky;       R[5] = -s * kx + ic * ky * kz;
        R[6] = -s * ky + ic * kz * kx; R[7] =  s * kx + ic * kz * ky; R[8] = c + ic * kz * kz;
    }
    #pragma unroll
    for (int q = 0; q < 6; q++) {
        int o = wid + 8 * q;
        int j = o / 3, d = o % 3;
        const float* jr = J_reg + j * NV;
        float acc = 0.f;
        #pragma unroll
        for (int k = 0; k < 25; k++) {
            int v = lane + 32 * k;
            if (v < NV) acc = fmaf(jr[v], s_vsh[v * 3 + d], acc);
        }
        #pragma unroll
        for (int off = 16; off > 0; off >>= 1) acc += __shfl_xor_sync(0xffffffffu, acc, off);
        if (lane == 0) s_J[o] = acc;
    }
    __syncthreads();

    // phase 3: pose features + kinematic chain (warp 0)
    if (tid >= 64 && tid < 64 + 135) {
        int p = tid - 64;
        int e = p % 9;
        float diag = ((e == 0) | (e == 4) | (e == 8)) ? 1.f : 0.f;
        s_pf[p] = s_R[(1 + p / 9) * 9 + e] - diag;
    }
    if (tid == 200) s_pf[135] = 0.f;
    if (wid == 0 && lane < 16) {
        const int j = lane;
        const int p = c_parents[j];
        float L[12];
        #pragma unroll
        for (int e = 0; e < 9; e++) L[(e / 3) * 4 + (e % 3)] = s_R[j * 9 + e];
        float jx = s_J[j * 3 + 0], jy = s_J[j * 3 + 1], jz = s_J[j * 3 + 2];
        if (j == 0) { L[3] = jx; L[7] = jy; L[11] = jz; }
        else {
            L[3]  = jx - s_J[p * 3 + 0];
            L[7]  = jy - s_J[p * 3 + 1];
            L[11] = jz - s_J[p * 3 + 2];
        }
        const int depth = (j == 0) ? 0 : ((j - 1) % 3) + 1;
        if (depth == 0) {
            #pragma unroll
            for (int k = 0; k < 12; k++) s_T[k] = L[k];
        }
        __syncwarp(0xffffu);
        #pragma unroll
        for (int l = 1; l <= 3; l++) {
            if (depth == l) {
                float Tp[12];
                #pragma unroll
                for (int k = 0; k < 12; k++) Tp[k] = s_T[p * 12 + k];
                #pragma unroll
                for (int r = 0; r < 3; r++) {
                    #pragma unroll
                    for (int c2 = 0; c2 < 4; c2++) {
                        float acc = (c2 == 3) ? Tp[r * 4 + 3] : 0.f;
                        #pragma unroll
                        for (int k = 0; k < 3; k++) acc = fmaf(Tp[r * 4 + k], L[k * 4 + c2], acc);
                        s_T[j * 12 + r * 4 + c2] = acc;
                    }
                }
            }
            __syncwarp(0xffffu);
        }
        #pragma unroll
        for (int r = 0; r < 3; r++) {
            float r0 = s_T[j * 12 + r * 4 + 0], r1 = s_T[j * 12 + r * 4 + 1], r2 = s_T[j * 12 + r * 4 + 2];
            s_A[j * 12 + r * 4 + 0] = r0;
            s_A[j * 12 + r * 4 + 1] = r1;
            s_A[j * 12 + r * 4 + 2] = r2;
            s_A[j * 12 + r * 4 + 3] = s_T[j * 12 + r * 4 + 3] - (r0 * jx + r1 * jy + r2 * jz);
        }
    }
    __syncthreads();

    // phase 4: posedirs einsum (warp-cooperative rows)
    float pfr[5];
    #pragma unroll
    for (int jj = 0; jj < 5; jj++) {
        int p = lane + 32 * jj;
        pfr[jj] = (p < 135) ? s_pf[p] : 0.f;
    }
    for (int r = wid; r < 49 * 3; r += 8) {
        int row = vbase * 3 + r;
        if (row < NV * 3) {
            const float* pd = posedirs + row * 135;
            float a = pfr[0] * pd[lane];
            a = fmaf(pfr[1], pd[lane + 32], a);
            a = fmaf(pfr[2], pd[lane + 64], a);
            a = fmaf(pfr[3], pd[lane + 96], a);
            if (lane < 7) a = fmaf(pfr[4], pd[lane + 128], a);
            #pragma unroll
            for (int off = 16; off > 0; off >>= 1)
                a += __shfl_xor_sync(0xffffffffu, a, off);
            if (lane == 0) s_vp[r] = s_vsh[row] + a;
        }
    }
    __syncthreads();

    // phase 5: LBS for 49 verts
    if (tid < 49) {
        int v = vbase + tid;
        if (v < NV) {
            const float4* w4 = (const float4*)(lbs_w + v * NJ);
            float4 a0 = w4[0], a1 = w4[1], a2 = w4[2], a3 = w4[3];
            float wj[16] = {a0.x,a0.y,a0.z,a0.w, a1.x,a1.y,a1.z,a1.w,
                            a2.x,a2.y,a2.z,a2.w, a3.x,a3.y,a3.z,a3.w};
            float M[12];
            #pragma unroll
            for (int k = 0; k < 12; k++) M[k] = 0.f;
            #pragma unroll
            for (int j = 0; j < NJ; j++) {
                #pragma unroll
                for (int k = 0; k < 12; k++) M[k] = fmaf(wj[j], s_A[j * 12 + k], M[k]);
            }
            float x = s_vp[tid * 3 + 0], y = s_vp[tid * 3 + 1], z = s_vp[tid * 3 + 2];
            float px = fmaf(M[0], x, fmaf(M[1],  y, fmaf(M[2],  z, M[3])))  + s_pose[0];
            float py = fmaf(M[4], x, fmaf(M[5],  y, fmaf(M[6],  z, M[7])))  + s_pose[1];
            float pz = fmaf(M[8], x, fmaf(M[9],  y, fmaf(M[10], z, M[11]))) + s_pose[2];
            out[OFF_VERTS + (b * NV + v) * 3 + 0] = px;
            out[OFF_VERTS + (b * NV + v) * 3 + 1] = py;
            out[OFF_VERTS + (b * NV + v) * 3 + 2] = pz;
            int p = v >> 1, i = v & 1;
            float* A = (float*)&g_vpA[b * NP + p];
            float* B = (float*)&g_vpB[b * NP + p];
            A[i] = px; A[2 + i] = py;
            B[i] = pz; B[2 + i] = -0.5f * (px * px + py * py + pz * pz);
        } else if (v < VP) {
            int p = v >> 1, i = v & 1;
            float* A = (float*)&g_vpA[b * NP + p];
            float* B = (float*)&g_vpB[b * NP + p];
            A[i] = 0.f; A[2 + i] = 0.f;
            B[i] = 0.f; B[2 + i] = -1e30f;   // sentinel: never wins
        }
    }
}

// ---------------------------------------------------------------------------
// scatter: face-normal accumulation (global atomics) + contact candidates
// ---------------------------------------------------------------------------
__global__ void __launch_bounds__(256) scatter_kernel(
    const int* __restrict__ faces, const float* __restrict__ aw,
    const int* __restrict__ afi, float* __restrict__ out)
{
    const int tid = threadIdx.x;
    if (blockIdx.x < 49) {
        int i = blockIdx.x * 256 + tid;
        if (i >= NB * FC) return;
        int b = i / FC, f = i % FC;
        const float* vb = out + OFF_VERTS + b * NV * 3;
        int i0 = faces[f * 3 + 0], i1 = faces[f * 3 + 1], i2 = faces[f * 3 + 2];
        float p0x = vb[i0*3+0], p0y = vb[i0*3+1], p0z = vb[i0*3+2];
        float e1x = vb[i1*3+0]-p0x, e1y = vb[i1*3+1]-p0y, e1z = vb[i1*3+2]-p0z;
        float e2x = vb[i2*3+0]-p0x, e2y = vb[i2*3+1]-p0y, e2z = vb[i2*3+2]-p0z;
        float nx = e1y * e2z - e1z * e2y;
        float ny = e1z * e2x - e1x * e2z;
        float nz = e1x * e2y - e1y * e2x;
        float* gn = g_normals + b * NV * 3;
        atomicAdd(&gn[i0*3+0], nx); atomicAdd(&gn[i0*3+1], ny); atomicAdd(&gn[i0*3+2], nz);
        atomicAdd(&gn[i1*3+0], nx); atomicAdd(&gn[i1*3+1], ny); atomicAdd(&gn[i1*3+2], nz);
        atomicAdd(&gn[i2*3+0], nx); atomicAdd(&gn[i2*3+1], ny); atomicAdd(&gn[i2*3+2], nz);
    } else {
        for (int t = tid; t < NB * NA * 3; t += 256) {
            int b = t / (NA * 3);
            int r = t % (NA * 3);
            int a = r / 3, d = r % 3;
            const float* vb = out + OFF_VERTS + b * NV * 3;
            float acc = 0.f;
            #pragma unroll
            for (int k = 0; k < 3; k++)
                acc = fmaf(aw[a * 3 + k], vb[afi[a * 3 + k] * 3 + d], acc);
            out[OFF_CC + t] = acc;
        }
    }
}

// ---------------------------------------------------------------------------
// nn: fused NN + cmap + penetration.
// 8-lane groups: lane g owns vertex chunk g, scans it for the group's 8
// points; recursive-halving merge (point p ends on lane p); lane g finishes
// point g with vectorized exact recovery. grid NB*128, 128 thr.
// packed f32x2: t = fma(X,OX, fma(Y,OY, fma(Z,OZ, Wn))) ; argmin d2==argmax t
// ---------------------------------------------------------------------------
__global__ void __launch_bounds__(128) nn_kernel(const float* __restrict__ obj,
                                                 float* __restrict__ out)
{
    __shared__ ulonglong2 s_a[NP];
    __shared__ ulonglong2 s_b[NP];
    __shared__ float s_red[4];

    const int b = blockIdx.x >> 7;
    const int tile = blockIdx.x & 127;
    const int tid = threadIdx.x;
    const int g = tid & 7;         // lane within group of 8 (owns chunk g)
    const int gq = tid >> 3;       // group id within block (0..15)

    for (int p = tid; p < NP; p += 128) {
        s_a[p] = g_vpA[b * NP + p];
        s_b[p] = g_vpB[b * NP + p];
    }
    __syncthreads();

    const int qbase = tile * 128 + gq * 8;   // group's 8 points
    const float4* o4 = (const float4*)(obj + (b * NOBJ + qbase) * 3);
    float4 f0 = o4[0], f1 = o4[1], f2 = o4[2], f3 = o4[3], f4 = o4[4], f5 = o4[5];
    unsigned long long X[8], Y[8], Z[8];
    X[0] = pack2(f0.x); Y[0] = pack2(f0.y); Z[0] = pack2(f0.z);
    X[1] = pack2(f0.w); Y[1] = pack2(f1.x); Z[1] = pack2(f1.y);
    X[2] = pack2(f1.z); Y[2] = pack2(f1.w); Z[2] = pack2(f2.x);
    X[3] = pack2(f2.y); Y[3] = pack2(f2.z); Z[3] = pack2(f2.w);
    X[4] = pack2(f3.x); Y[4] = pack2(f3.y); Z[4] = pack2(f3.z);
    X[5] = pack2(f3.w); Y[5] = pack2(f4.x); Z[5] = pack2(f4.y);
    X[6] = pack2(f4.z); Y[6] = pack2(f4.w); Z[6] = pack2(f5.x);
    X[7] = pack2(f5.y); Y[7] = pack2(f5.z); Z[7] = pack2(f5.w);

    float v[8];
    #pragma unroll
    for (int p = 0; p < 8; p++) v[p] = -3.4e38f;

    const ulonglong2* pa = s_a + g * CPL;
    const ulonglong2* pb = s_b + g * CPL;
    #pragma unroll 2
    for (int k = 0; k < CPL; k++) {
        ulonglong2 A = pa[k], B = pb[k];
        #pragma unroll
        for (int p = 0; p < 8; p++) {
            unsigned long long t; float lo, hi;
            FMA2(t, B.x, Z[p], B.y);
            FMA2(t, A.y, Y[p], t);
            FMA2(t, A.x, X[p], t);
            unpack2(t, lo, hi);
            v[p] = fmaxf(v[p], lo);
            v[p] = fmaxf(v[p], hi);
        }
    }

    // recursive-halving merge with (max, min-chunk-on-tie) semiring.
    // After round r, lane keeps points whose bit matches its own; point p
    // ends on lane p. Associativity => global first-argmin preserved.
    const unsigned FULLM = 0xffffffffu;
    float w[4]; int d[4];
    {
        const bool h4 = (g & 4) != 0;
        #pragma unroll
        for (int k = 0; k < 4; k++) {
            float sv = h4 ? v[k] : v[4 + k];
            float rv = __shfl_xor_sync(FULLM, sv, 4);
            float mv = h4 ? v[4 + k] : v[k];
            int rc = g ^ 4, mc = g;          // chunk ids known in round 1
            bool take = (rv > mv) || (rv == mv && rc < mc);
            w[k] = take ? rv : mv;
            d[k] = take ? rc : mc;
        }
    }
    float u[2]; int e[2];
    {
        const bool h2 = (g & 2) != 0;
        #pragma unroll
        for (int k = 0; k < 2; k++) {
            float sv = h2 ? w[k] : w[2 + k];
            int   sc = h2 ? d[k] : d[2 + k];
            float rv = __shfl_xor_sync(FULLM, sv, 2);
            int   rc = __shfl_xor_sync(FULLM, sc, 2);
            float mv = h2 ? w[2 + k] : w[k];
            int   mc = h2 ? d[2 + k] : d[k];
            bool take = (rv > mv) || (rv == mv && rc < mc);
            u[k] = take ? rv : mv;
            e[k] = take ? rc : mc;
        }
    }
    float best; int bc;
    {
        const bool h1 = (g & 1) != 0;
        float sv = h1 ? u[0] : u[1];
        int   sc = h1 ? e[0] : e[1];
        float rv = __shfl_xor_sync(FULLM, sv, 1);
        int   rc = __shfl_xor_sync(FULLM, sc, 1);
        float mv = h1 ? u[1] : u[0];
        int   mc = h1 ? e[1] : e[0];
        bool take = (rv > mv) || (rv == mv && rc < mc);
        best = take ? rv : mv;
        bc   = take ? rc : mc;
    }

    // lane g finishes point qbase+g
    const int pt = qbase + g;
    const float* op = obj + (b * NOBJ + pt) * 3;
    const float ox = op[0], oy = op[1], oz = op[2];

    // vectorized exact in-order index recovery (identical FMA2 chain as scan)
    const unsigned long long OX = pack2(ox), OY = pack2(oy), OZ = pack2(oz);
    const ulonglong2* ra = s_a + bc * CPL;
    const ulonglong2* rb = s_b + bc * CPL;
    int idx = -1;
    for (int k = 0; k < CPL; k++) {
        ulonglong2 A = ra[k], B = rb[k];
        unsigned long long t; float lo, hi;
        FMA2(t, B.x, OZ, B.y); FMA2(t, A.y, OY, t); FMA2(t, A.x, OX, t);
        unpack2(t, lo, hi);
        if (idx < 0 && lo == best) idx = 2 * k;
        if (idx < 0 && hi == best) idx = 2 * k + 1;
    }
    const int bi = bc * (2 * CPL) + idx;

    float o2 = ox * ox + oy * oy + oz * oz;
    float d2 = fmaf(-2.f, best, o2);
    out[OFF_CMAP + b * NOBJ + pt] = 2.f / (1.f + __expf(100.f * d2));

    int pp = bi >> 1, ii = bi & 1;
    const float* Af = (const float*)&s_a[pp];
    const float* Bf = (const float*)&s_b[pp];
    float vx = Af[ii], vy = Af[2 + ii], vz = Bf[ii];
    const float* gn = g_normals + (b * NV + bi) * 3;
    float dp = (vx - ox) * gn[0] + (vy - oy) * gn[1] + (vz - oz) * gn[2];
    float pen = (dp > 0.f) ? d2 : 0.f;

    #pragma unroll
    for (int off = 16; off > 0; off >>= 1) pen += __shfl_down_sync(0xffffffffu, pen, off);
    if ((tid & 31) == 0) s_red[tid >> 5] = pen;
    __syncthreads();
    if (tid == 0) {
        float s = s_red[0] + s_red[1] + s_red[2] + s_red[3];
        atomicAdd(&out[OFF_PEN], s * (1.f / NB));
    }
}

// ---------------------------------------------------------------------------
extern "C" void kernel_launch(void* const* d_in, const int* in_sizes, int n_in,
                              void* d_out, int out_size)
{
    const float* hand_pose  = (const float*)d_in[0];
    const float* obj_points = (const float*)d_in[1];
    const float* hand_beta  = (const float*)d_in[2];
    const float* v_template = (const float*)d_in[3];
    const float* shapedirs  = (const float*)d_in[4];
    const float* posedirs   = (const float*)d_in[5];
    const float* J_reg      = (const float*)d_in[6];
    const float* lbs_w      = (const float*)d_in[7];
    const float* pca        = (const float*)d_in[8];
    const float* aw         = (const float*)d_in[9];
    const int*   faces      = (const int*)d_in[10];
    const int*   afi        = (const int*)d_in[11];
    float* out = (float*)d_out;

    vert_kernel<<<NB * 16, 256>>>(v_template, shapedirs, posedirs, lbs_w,
                                  hand_pose, hand_beta, pca, J_reg, out);
    scatter_kernel<<<50, 256>>>(faces, aw, afi, out);
    nn_kernel<<<NB * 128, 128>>>(obj_points, out);
}